// round 5
// baseline (speedup 1.0000x reference)
#include <cuda_runtime.h>

#define DIMC 192
#define RJ   48          // DIM / RED
#define BB   4
#define HH   256
#define WW   256
#define HWSZ (HH * WW)   // 65536
#define EPSV 1e-5f

#define PSEGS 2                        // segments per plane in pool job
#define POOL_BLOCKS (DIMC * PSEGS)     // 384 pool blocks (512 threads)
#define ROWS_PER_BLK 16                // conv: 16 warps = 16 rows per block
#define CONV_BLOCKS (DIMC * (HH / ROWS_PER_BLK))   // 192*16 = 3072 blocks

// Scratch (device globals; no allocation allowed).
__device__ float        g_part[DIMC * PSEGS];  // per-batch partials (batches serialize)
__device__ float        g_wt[BB * DIMC * 4];   // 4 surviving masked taps per (b,c)
__device__ unsigned int g_cnt = 0;             // wraps to 0 each batch (replay-safe)

// ---------------------------------------------------------------------------
// Pool job for batch pb: 384 blocks x 512 threads; last block runs weight-gen.
// Normal (caching) loads on purpose: fills L2 with exactly what conv(pb) reads.
// ---------------------------------------------------------------------------
__device__ __forceinline__ void pool_job(
        const float* __restrict__ x, int pb, int pblk,
        const float* __restrict__ w1,  const float* __restrict__ gamma,
        const float* __restrict__ beta, const float* __restrict__ rmean,
        const float* __restrict__ rvar, const float* __restrict__ w2,
        const float* __restrict__ b2) {
    const int c   = pblk >> 1;
    const int seg = pblk & 1;
    const int tid = threadIdx.x;

    const float4* p = (const float4*)(x + ((size_t)(pb * DIMC + c)) * HWSZ)
                      + seg * (HWSZ / 4 / PSEGS);
    float s = 0.f;
    #pragma unroll
    for (int i = 0; i < HWSZ / 4 / PSEGS / 512; i++) {   // 16 independent loads
        float4 v = p[tid + i * 512];
        s += (v.x + v.y) + (v.z + v.w);
    }
    #pragma unroll
    for (int o = 16; o > 0; o >>= 1) s += __shfl_down_sync(0xffffffffu, s, o);
    __shared__ float sm[16];
    const int lane = tid & 31, wrp = tid >> 5;
    if (lane == 0) sm[wrp] = s;
    __syncthreads();
    __shared__ bool is_last;
    if (tid == 0) {
        float t = 0.f;
        #pragma unroll
        for (int i = 0; i < 16; i++) t += sm[i];
        g_part[c * PSEGS + seg] = t;
        __threadfence();
        unsigned int old = atomicInc(&g_cnt, POOL_BLOCKS - 1);   // 383 -> 0
        is_last = (old == POOL_BLOCKS - 1);
    }
    __syncthreads();
    if (!is_last) return;

    // ---- weight-gen tail for batch pb ----
    __shared__ float pooled[DIMC];
    __shared__ float t48[RJ];
    if (tid < DIMC) {
        const float* gp = g_part + tid * PSEGS;
        pooled[tid] = (gp[0] + gp[1]) * (1.0f / (float)HWSZ);
    }
    __syncthreads();
    if (tid < RJ) {
        const float* pw = w1 + tid * DIMC;
        float acc = 0.f;
        #pragma unroll 8
        for (int cc = 0; cc < DIMC; cc++) acc = fmaf(pooled[cc], pw[cc], acc);
        acc = gamma[tid] * (acc - rmean[tid]) * rsqrtf(rvar[tid] + EPSV) + beta[tid];
        t48[tid] = fmaxf(acc, 0.f);
    }
    __syncthreads();
    for (int idx = tid; idx < DIMC * 4; idx += 512) {    // mask 'A' taps 0..3
        const int cc = idx >> 2;
        const int k  = idx & 3;
        const int o  = cc * 9 + k;
        const float* pw2 = w2 + (size_t)o * RJ;
        float acc = b2[o];
        #pragma unroll
        for (int j = 0; j < RJ; j++) acc = fmaf(t48[j], pw2[j], acc);
        g_wt[(pb * DIMC + cc) * 4 + k] = acc;
    }
}

// ---------------------------------------------------------------------------
// Conv job: one warp = one image row, 8 outputs per thread.
//   out(y,x) = w0*in(y-1,x-1)+w1*in(y-1,x)+w2*in(y-1,x+1)+w3*in(y,x-1)+bias
// 4 independent LDG.128 + 3 scalar halo loads per thread (MLP~7).
// __ldcs reads (L2-resident from pool; evict-first), __stcs streaming writes.
// ---------------------------------------------------------------------------
__device__ __forceinline__ void conv_job(
        const float* __restrict__ x, const float* __restrict__ bias,
        float* __restrict__ out, int cb, int cblk) {
    const int c      = cblk >> 4;                   // 0..191
    const int rowblk = cblk & 15;
    const int bc = cb * DIMC + c;
    const float4 wv = *(const float4*)(g_wt + bc * 4);
    const float w0 = wv.x, w1 = wv.y, w2 = wv.z, w3 = wv.w;
    const float bs = bias[c];

    const int lane = threadIdx.x & 31;
    const int y    = rowblk * ROWS_PER_BLK + (threadIdx.x >> 5);
    const int x0   = lane << 3;                     // 8 floats per thread

    const float* base = x + (size_t)bc * HWSZ;
    const float* rowc = base + y * WW;
    const float* rowm = rowc - WW;

    // current row: x0 .. x0+7, plus x0-1
    const float4 b0 = __ldcs((const float4*)(rowc + x0));
    const float4 b1 = __ldcs((const float4*)(rowc + x0 + 4));
    float bm1 = (lane > 0) ? rowc[x0 - 1] : 0.f;

    // row above: x0-1 .. x0+8
    float4 a0, a1; float am1, ap8;
    if (y > 0) {                                     // warp-uniform
        a0  = __ldcs((const float4*)(rowm + x0));
        a1  = __ldcs((const float4*)(rowm + x0 + 4));
        am1 = (lane > 0)  ? rowm[x0 - 1] : 0.f;
        ap8 = (lane < 31) ? rowm[x0 + 8] : 0.f;
    } else {
        a0 = make_float4(0.f,0.f,0.f,0.f); a1 = a0; am1 = 0.f; ap8 = 0.f;
    }

    const float A[10] = {am1, a0.x, a0.y, a0.z, a0.w, a1.x, a1.y, a1.z, a1.w, ap8};
    const float Bv[8] = {bm1, b0.x, b0.y, b0.z, b0.w, b1.x, b1.y, b1.z};

    float o[8];
    #pragma unroll
    for (int i = 0; i < 8; i++)
        o[i] = fmaf(w0, A[i], fmaf(w1, A[i+1], fmaf(w2, A[i+2], fmaf(w3, Bv[i], bs))));

    float* po = out + (size_t)bc * HWSZ + y * WW + x0;
    __stcs((float4*)po,     make_float4(o[0], o[1], o[2], o[3]));
    __stcs((float4*)po + 1, make_float4(o[4], o[5], o[6], o[7]));
}

// ---------------------------------------------------------------------------
// Kernels — __launch_bounds__(512, 3): <=42 regs, 75% occupancy.
// ---------------------------------------------------------------------------
__global__ __launch_bounds__(512, 3) void pool_only_kernel(
        const float* __restrict__ x, int pb,
        const float* __restrict__ w1, const float* __restrict__ gamma,
        const float* __restrict__ beta, const float* __restrict__ rmean,
        const float* __restrict__ rvar, const float* __restrict__ w2,
        const float* __restrict__ b2) {
    pool_job(x, pb, blockIdx.x, w1, gamma, beta, rmean, rvar, w2, b2);
}

__global__ __launch_bounds__(512, 3) void fused_kernel(
        const float* __restrict__ x, const float* __restrict__ bias,
        float* __restrict__ out, int cb,
        const float* __restrict__ w1, const float* __restrict__ gamma,
        const float* __restrict__ beta, const float* __restrict__ rmean,
        const float* __restrict__ rvar, const float* __restrict__ w2,
        const float* __restrict__ b2) {
    if (blockIdx.x < POOL_BLOCKS) {
        pool_job(x, cb + 1, blockIdx.x, w1, gamma, beta, rmean, rvar, w2, b2);
    } else {
        conv_job(x, bias, out, cb, blockIdx.x - POOL_BLOCKS);
    }
}

__global__ __launch_bounds__(512, 3) void conv_only_kernel(
        const float* __restrict__ x, const float* __restrict__ bias,
        float* __restrict__ out, int cb) {
    conv_job(x, bias, out, cb, blockIdx.x);
}

// ---------------------------------------------------------------------------
extern "C" void kernel_launch(void* const* d_in, const int* in_sizes, int n_in,
                              void* d_out, int out_size) {
    const float* x     = (const float*)d_in[0];
    const float* w1    = (const float*)d_in[1];
    const float* gamma = (const float*)d_in[2];
    const float* beta  = (const float*)d_in[3];
    const float* rmean = (const float*)d_in[4];
    const float* rvar  = (const float*)d_in[5];
    const float* w2    = (const float*)d_in[6];
    const float* b2    = (const float*)d_in[7];
    const float* bias  = (const float*)d_in[8];
    float* out = (float*)d_out;

    pool_only_kernel<<<POOL_BLOCKS, 512>>>(x, 0, w1, gamma, beta,
                                           rmean, rvar, w2, b2);
    for (int b = 0; b < BB - 1; b++) {
        fused_kernel<<<POOL_BLOCKS + CONV_BLOCKS, 512>>>(
            x, bias, out, b, w1, gamma, beta, rmean, rvar, w2, b2);
    }
    conv_only_kernel<<<CONV_BLOCKS, 512>>>(x, bias, out, BB - 1);
}

// round 6
// speedup vs baseline: 1.5438x; 1.5438x over previous
#include <cuda_runtime.h>

#define DIMC 192
#define RJ   48          // DIM / RED
#define BB   4
#define HH   256
#define WW   256
#define HWSZ (HH * WW)   // 65536
#define EPSV 1e-5f

// Scratch (no device allocation allowed).
__device__ float g_pooled[BB * DIMC];        // [b*DIM + c]
__device__ float g_wt[BB * DIMC * 4];        // 4 surviving masked taps per (b,c)

// ---------------------------------------------------------------------------
// Kernel 1: global average pool per (b,c). One block per channel plane.
// Proven at the LTS/HBM ceiling (6.1 TB/s) — unchanged from R1.
// ---------------------------------------------------------------------------
__global__ void pool_kernel(const float* __restrict__ x) {
    const int bc = blockIdx.x;                       // 0..767
    const float4* p = (const float4*)(x + (size_t)bc * HWSZ);
    const int n4 = HWSZ / 4;                         // 16384
    float s = 0.f;
    for (int i = threadIdx.x; i < n4; i += blockDim.x) {
        float4 v = p[i];
        s += (v.x + v.y) + (v.z + v.w);
    }
    #pragma unroll
    for (int o = 16; o > 0; o >>= 1) s += __shfl_down_sync(0xffffffffu, s, o);
    __shared__ float sm[32];
    const int lane = threadIdx.x & 31;
    const int wrp  = threadIdx.x >> 5;
    if (lane == 0) sm[wrp] = s;
    __syncthreads();
    if (wrp == 0) {
        s = (lane < (int)(blockDim.x >> 5)) ? sm[lane] : 0.f;
        #pragma unroll
        for (int o = 16; o > 0; o >>= 1) s += __shfl_down_sync(0xffffffffu, s, o);
        if (lane == 0) g_pooled[bc] = s * (1.0f / (float)HWSZ);
    }
}

// ---------------------------------------------------------------------------
// Kernel 2: dynamic weight generation (tiny, unchanged).
// ---------------------------------------------------------------------------
__global__ void wgen_kernel(const float* __restrict__ w1,
                            const float* __restrict__ gamma,
                            const float* __restrict__ beta,
                            const float* __restrict__ rmean,
                            const float* __restrict__ rvar,
                            const float* __restrict__ w2,
                            const float* __restrict__ b2) {
    const int b   = blockIdx.x;
    const int tid = threadIdx.x;
    __shared__ float t[RJ];

    if (tid < RJ) {
        const float* pw = w1 + tid * DIMC;
        const float* pp = g_pooled + b * DIMC;
        float acc = 0.f;
        #pragma unroll 8
        for (int c = 0; c < DIMC; c++) acc = fmaf(pp[c], pw[c], acc);
        acc = gamma[tid] * (acc - rmean[tid]) * rsqrtf(rvar[tid] + EPSV) + beta[tid];
        t[tid] = fmaxf(acc, 0.f);
    }
    __syncthreads();

    // tid -> (channel c, tap k). Mask 'A' keeps 3x3 positions 0..3.
    const int c = tid >> 2;
    const int k = tid & 3;
    const int o = c * 9 + k;
    const float* pw2 = w2 + (size_t)o * RJ;
    float acc = b2[o];
    #pragma unroll
    for (int j = 0; j < RJ; j++) acc = fmaf(t[j], pw2[j], acc);
    g_wt[(b * DIMC + c) * 4 + k] = acc;
}

// ---------------------------------------------------------------------------
// Kernel 3: masked depthwise conv. Active taps:
//   out(y,x) = w0*in(y-1,x-1)+w1*in(y-1,x)+w2*in(y-1,x+1)+w3*in(y,x-1)+bias
// One warp = one image row (32 lanes x 8 floats = 256). Per thread:
// 4 independent LDG.128 + 3 scalar halo loads (MLP~7), 2 STG.128.
// Blocks of 256 threads cover 8 rows; halo rows L1-hit from neighbor warps.
// ---------------------------------------------------------------------------
__global__ __launch_bounds__(256) void conv_kernel(const float* __restrict__ x,
                                                   const float* __restrict__ bias,
                                                   float* __restrict__ out) {
    const int bc = blockIdx.y;                      // 0..767
    const int c  = bc % DIMC;
    const float4 wv = *(const float4*)(g_wt + bc * 4);
    const float w0 = wv.x, w1 = wv.y, w2 = wv.z, w3 = wv.w;
    const float bs = bias[c];

    const int lane = threadIdx.x & 31;
    const int y    = blockIdx.x * 8 + (threadIdx.x >> 5);
    const int x0   = lane << 3;                     // 8 floats per thread

    const float* base = x + (size_t)bc * HWSZ;
    const float* rowc = base + y * WW;
    const float* rowm = rowc - WW;                  // deref'd only when y>0 (warp-uniform)

    // current row: x0 .. x0+7, plus x0-1
    const float4 b0 = __ldcs((const float4*)(rowc + x0));
    const float4 b1 = __ldcs((const float4*)(rowc + x0 + 4));
    const float  bm1 = (lane > 0) ? rowc[x0 - 1] : 0.f;

    // row above: x0-1 .. x0+8
    float4 a0, a1; float am1, ap8;
    if (y > 0) {                                     // warp-uniform
        a0  = __ldcs((const float4*)(rowm + x0));
        a1  = __ldcs((const float4*)(rowm + x0 + 4));
        am1 = (lane > 0)  ? rowm[x0 - 1] : 0.f;
        ap8 = (lane < 31) ? rowm[x0 + 8] : 0.f;
    } else {
        a0 = make_float4(0.f, 0.f, 0.f, 0.f); a1 = a0; am1 = 0.f; ap8 = 0.f;
    }

    const float A[10]  = {am1, a0.x, a0.y, a0.z, a0.w, a1.x, a1.y, a1.z, a1.w, ap8};
    const float Bv[8]  = {bm1, b0.x, b0.y, b0.z, b0.w, b1.x, b1.y, b1.z};

    float o[8];
    #pragma unroll
    for (int i = 0; i < 8; i++)
        o[i] = fmaf(w0, A[i], fmaf(w1, A[i+1], fmaf(w2, A[i+2], fmaf(w3, Bv[i], bs))));

    float* po = out + (size_t)bc * HWSZ + y * WW + x0;
    __stcs((float4*)po,     make_float4(o[0], o[1], o[2], o[3]));
    __stcs((float4*)po + 1, make_float4(o[4], o[5], o[6], o[7]));
}

// ---------------------------------------------------------------------------
extern "C" void kernel_launch(void* const* d_in, const int* in_sizes, int n_in,
                              void* d_out, int out_size) {
    const float* x     = (const float*)d_in[0];
    const float* w1    = (const float*)d_in[1];
    const float* gamma = (const float*)d_in[2];
    const float* beta  = (const float*)d_in[3];
    const float* rmean = (const float*)d_in[4];
    const float* rvar  = (const float*)d_in[5];
    const float* w2    = (const float*)d_in[6];
    const float* b2    = (const float*)d_in[7];
    const float* bias  = (const float*)d_in[8];
    float* out = (float*)d_out;

    pool_kernel<<<BB * DIMC, 256>>>(x);
    wgen_kernel<<<BB, DIMC * 4>>>(w1, gamma, beta, rmean, rvar, w2, b2);

    dim3 grid(HH / 8, BB * DIMC);                   // (32, 768)
    conv_kernel<<<grid, 256>>>(x, bias, out);
}

// round 7
// speedup vs baseline: 1.6377x; 1.0608x over previous
#include <cuda_runtime.h>

#define DIMC 192
#define RJ   48          // DIM / RED
#define BB   4
#define HH   256
#define WW   256
#define HWSZ (HH * WW)   // 65536
#define EPSV 1e-5f

// Scratch (no device allocation allowed).
__device__ float g_pooled[BB * DIMC];        // [b*DIM + c]
__device__ float g_wt[BB * DIMC * 4];        // 4 surviving masked taps per (b,c)

// ---------------------------------------------------------------------------
// Kernel 1: global average pool per (b,c). One block per channel plane.
// Reads planes in FORWARD order (bc = 0..767); conv consumes in reverse.
// At the LTS/HBM ceiling (6.25 TB/s).
// ---------------------------------------------------------------------------
__global__ void pool_kernel(const float* __restrict__ x) {
    const int bc = blockIdx.x;                       // 0..767
    const float4* p = (const float4*)(x + (size_t)bc * HWSZ);
    const int n4 = HWSZ / 4;                         // 16384
    float s = 0.f;
    for (int i = threadIdx.x; i < n4; i += blockDim.x) {
        float4 v = p[i];
        s += (v.x + v.y) + (v.z + v.w);
    }
    #pragma unroll
    for (int o = 16; o > 0; o >>= 1) s += __shfl_down_sync(0xffffffffu, s, o);
    __shared__ float sm[32];
    const int lane = threadIdx.x & 31;
    const int wrp  = threadIdx.x >> 5;
    if (lane == 0) sm[wrp] = s;
    __syncthreads();
    if (wrp == 0) {
        s = (lane < (int)(blockDim.x >> 5)) ? sm[lane] : 0.f;
        #pragma unroll
        for (int o = 16; o > 0; o >>= 1) s += __shfl_down_sync(0xffffffffu, s, o);
        if (lane == 0) g_pooled[bc] = s * (1.0f / (float)HWSZ);
    }
}

// ---------------------------------------------------------------------------
// Kernel 2: dynamic weight generation (tiny, unchanged).
// ---------------------------------------------------------------------------
__global__ void wgen_kernel(const float* __restrict__ w1,
                            const float* __restrict__ gamma,
                            const float* __restrict__ beta,
                            const float* __restrict__ rmean,
                            const float* __restrict__ rvar,
                            const float* __restrict__ w2,
                            const float* __restrict__ b2) {
    const int b   = blockIdx.x;
    const int tid = threadIdx.x;
    __shared__ float t[RJ];

    if (tid < RJ) {
        const float* pw = w1 + tid * DIMC;
        const float* pp = g_pooled + b * DIMC;
        float acc = 0.f;
        #pragma unroll 8
        for (int c = 0; c < DIMC; c++) acc = fmaf(pp[c], pw[c], acc);
        acc = gamma[tid] * (acc - rmean[tid]) * rsqrtf(rvar[tid] + EPSV) + beta[tid];
        t[tid] = fmaxf(acc, 0.f);
    }
    __syncthreads();

    // tid -> (channel c, tap k). Mask 'A' keeps 3x3 positions 0..3.
    const int c = tid >> 2;
    const int k = tid & 3;
    const int o = c * 9 + k;
    const float* pw2 = w2 + (size_t)o * RJ;
    float acc = b2[o];
    #pragma unroll
    for (int j = 0; j < RJ; j++) acc = fmaf(t[j], pw2[j], acc);
    g_wt[(b * DIMC + c) * 4 + k] = acc;
}

// ---------------------------------------------------------------------------
// Kernel 3: masked depthwise conv. Active taps:
//   out(y,x) = w0*in(y-1,x-1)+w1*in(y-1,x)+w2*in(y-1,x+1)+w3*in(y,x-1)+bias
// One warp = one full image row (32 lanes x 8). Exactly 4 LDG.128 + 2 STG.128
// per thread; ALL halos via warp shuffles (lane 0/31 give true edge zeros).
// Planes consumed in REVERSE pool order -> L2 hits on recently-pooled data.
// ---------------------------------------------------------------------------
__global__ __launch_bounds__(256) void conv_kernel(const float* __restrict__ x,
                                                   const float* __restrict__ bias,
                                                   float* __restrict__ out) {
    const int bc = (BB * DIMC - 1) - blockIdx.y;    // reversed: 767..0
    const int c  = bc % DIMC;
    const float4 wv = *(const float4*)(g_wt + bc * 4);
    const float w0 = wv.x, w1 = wv.y, w2 = wv.z, w3 = wv.w;
    const float bs = bias[c];

    const int lane = threadIdx.x & 31;
    const int y    = blockIdx.x * 8 + (threadIdx.x >> 5);
    const int x0   = lane << 3;                     // 8 floats per thread

    const float* base = x + (size_t)bc * HWSZ;
    const float* rowc = base + y * WW;
    const float* rowm = rowc - WW;                  // deref'd only when y>0 (warp-uniform)

    // current row: x0 .. x0+7
    const float4 b0 = __ldcs((const float4*)(rowc + x0));
    const float4 b1 = __ldcs((const float4*)(rowc + x0 + 4));

    // row above: x0 .. x0+7
    float4 a0, a1;
    if (y > 0) {                                     // warp-uniform
        a0 = __ldcs((const float4*)(rowm + x0));
        a1 = __ldcs((const float4*)(rowm + x0 + 4));
    } else {
        a0 = make_float4(0.f, 0.f, 0.f, 0.f); a1 = a0;
    }

    // Halos entirely from neighbor lanes; warp spans the full row, so lane 0
    // shfl_up and lane 31 shfl_down correspond to the zero-padded image edges.
    float am1 = __shfl_up_sync(0xffffffffu, a1.w, 1);
    float bm1 = __shfl_up_sync(0xffffffffu, b1.w, 1);
    float ap8 = __shfl_down_sync(0xffffffffu, a0.x, 1);
    if (lane == 0)  { am1 = 0.f; bm1 = 0.f; }
    if (lane == 31) { ap8 = 0.f; }

    const float A[10] = {am1, a0.x, a0.y, a0.z, a0.w, a1.x, a1.y, a1.z, a1.w, ap8};
    const float Bv[8] = {bm1, b0.x, b0.y, b0.z, b0.w, b1.x, b1.y, b1.z};

    float o[8];
    #pragma unroll
    for (int i = 0; i < 8; i++)
        o[i] = fmaf(w0, A[i], fmaf(w1, A[i+1], fmaf(w2, A[i+2], fmaf(w3, Bv[i], bs))));

    float* po = out + (size_t)bc * HWSZ + y * WW + x0;
    __stcs((float4*)po,     make_float4(o[0], o[1], o[2], o[3]));
    __stcs((float4*)po + 1, make_float4(o[4], o[5], o[6], o[7]));
}

// ---------------------------------------------------------------------------
extern "C" void kernel_launch(void* const* d_in, const int* in_sizes, int n_in,
                              void* d_out, int out_size) {
    const float* x     = (const float*)d_in[0];
    const float* w1    = (const float*)d_in[1];
    const float* gamma = (const float*)d_in[2];
    const float* beta  = (const float*)d_in[3];
    const float* rmean = (const float*)d_in[4];
    const float* rvar  = (const float*)d_in[5];
    const float* w2    = (const float*)d_in[6];
    const float* b2    = (const float*)d_in[7];
    const float* bias  = (const float*)d_in[8];
    float* out = (float*)d_out;

    pool_kernel<<<BB * DIMC, 256>>>(x);
    wgen_kernel<<<BB, DIMC * 4>>>(w1, gamma, beta, rmean, rvar, w2, b2);

    dim3 grid(HH / 8, BB * DIMC);                   // (32, 768), y = reversed plane
    conv_kernel<<<grid, 256>>>(x, bias, out);
}